// round 8
// baseline (speedup 1.0000x reference)
#include <cuda_runtime.h>
#include <math.h>

// Problem constants (fixed by setup_inputs): N=16, T=2048, D=2
#define TT 2048
#define NBMAX 16
#define LOG2PI_F 1.8378770664093453f
#define LN2F     0.6931471805599453f

// Scratch (device globals; no allocation allowed)
__device__ float4 g_pack[NBMAX * TT];   // (A_j, xs_j, ys_j, 0)
__device__ float  g_logP[NBMAX * TT];   // log( sum_{j<i} exp(t_j/sp) )

__device__ __forceinline__ float ex2f(float x) {
    float r;
    asm("ex2.approx.f32 %0, %1;" : "=f"(r) : "f"(x));
    return r;
}

// ---------------------------------------------------------------------------
// Kernel A: per batch, build packed per-j data and prefix logP.
// ---------------------------------------------------------------------------
__global__ void prep_kernel(const float* __restrict__ tim,
                            const float* __restrict__ loc,
                            const float* __restrict__ cd_p,
                            const float* __restrict__ sls_p) {
    const int n   = blockIdx.x;
    const int tid = threadIdx.x;           // 256 threads
    const float cd  = *cd_p;
    const float sls = *sls_p;
    const float sp  = log1pf(__expf(cd));          // softplus(coeff_decay)
    const float rc2 = 1.0f / (sp * LN2F);
    const float h2l = 0.5f * __expf(-2.0f * sls) / LN2F;

    __shared__ float sE[TT];
    __shared__ float wtot[8];
    __shared__ float wbase[8];

    for (int j = tid; j < TT; j += 256) {
        float tj = tim[n * TT + j];
        float xj = loc[(n * TT + j) * 2 + 0];
        float yj = loc[(n * TT + j) * 2 + 1];
        float c2 = tj * rc2;
        float A  = fmaf(-h2l, fmaf(xj, xj, yj * yj), c2);
        float xs = 2.0f * h2l * xj;
        float ys = 2.0f * h2l * yj;
        g_pack[n * TT + j] = make_float4(A, xs, ys, 0.0f);
        sE[j] = ex2f(c2);
    }
    __syncthreads();

    const int C = TT / 256;                // 8
    float part = 0.0f;
#pragma unroll
    for (int kk = 0; kk < C; kk++) part += sE[tid * C + kk];

    float inc = part;
    const int lane = tid & 31;
#pragma unroll
    for (int o = 1; o < 32; o <<= 1) {
        float v = __shfl_up_sync(0xffffffffu, inc, o);
        if (lane >= o) inc += v;
    }
    if (lane == 31) wtot[tid >> 5] = inc;
    __syncthreads();
    if (tid < 8) {
        float v = wtot[tid], s = v;
#pragma unroll
        for (int o = 1; o < 8; o <<= 1) {
            float u = __shfl_up_sync(0x000000ffu, s, o);
            if (tid >= o) s += u;
        }
        wbase[tid] = s - v;
    }
    __syncthreads();

    float run = wbase[tid >> 5] + (inc - part);
#pragma unroll
    for (int kk = 0; kk < C; kk++) {
        int j = tid * C + kk;
        g_logP[n * TT + j] = (j == 0) ? 0.0f : __logf(run);
        run += sE[j];
    }
}

// ---------------------------------------------------------------------------
// Kernel B: block = (batch n, slice k of 16); 4 tiles {k, k+16, 63-k, 47-k},
// each tile's dense j-range split between a warp pair:
//   wid 0/1: tile k      lower/upper
//   wid 2/3: tile k+16   lower/upper
//   wid 4/5: tile 63-k   lower/upper
//   wid 6/7: tile 47-k   lower/upper
// SMSP s receives wid s and s+4 -> 16k' + 16(63-k') = 1008 j  (uniform).
// Tails (31 predicated j) on wid 0, 5, 2, 7 -> one per SMSP.
// Double-buffered 4KB smem staging of g_pack; LDS broadcast in inner loop.
// Grid = 16*16 = 256 blocks, 2 blocks/SM -> 4 warps/SMSP.
// ---------------------------------------------------------------------------
__global__ void __launch_bounds__(256, 2)
main_kernel(const float* __restrict__ loc,
            const float* __restrict__ mu0_p,
            const float* __restrict__ ls0_p,
            const float* __restrict__ sls_p,
            float* __restrict__ out) {
    const int b    = blockIdx.x;
    const int n    = b >> 4;               // batch
    const int k    = b & 15;               // slice
    const int tid  = threadIdx.x;
    const int wid  = tid >> 5;
    const int lane = tid & 31;

    // tile for this warp (pairs share a tile)
    const int pairid = wid >> 1;           // 0..3
    int tile;
    switch (pairid) {
        case 0:  tile = k;       break;
        case 1:  tile = k + 16;  break;
        case 2:  tile = 63 - k;  break;
        default: tile = 47 - k;  break;
    }
    const bool upper  = wid & 1;
    const int  jstart = upper ? (tile << 4) : 0;
    const int  jend   = upper ? (tile << 5) : (tile << 4);
    const bool dotail = (wid == 0) | (wid == 5) | (wid == 2) | (wid == 7);
    // tail tile == this warp's tile for those wids (0->k, 5->63-k, 2->k+16, 7->47-k)

    const int rmax    = 63 - k;
    const int nchunks = ((rmax << 5) + 31 + 255) >> 8;

    __shared__ float4 sb[2][256];
    __shared__ float  sacc[8][32];

    const float sls = *sls_p;
    const float h2l = 0.5f * __expf(-2.0f * sls) / LN2F;

    const int i = (tile << 5) + lane;
    const float xi = loc[(n * TT + i) * 2 + 0];
    const float yi = loc[(n * TT + i) * 2 + 1];

    const float4* __restrict__ pk = &g_pack[n * TT];

    sb[0][tid] = pk[tid];
    __syncthreads();

    float s0 = 0.0f, s1 = 0.0f, s2 = 0.0f, s3 = 0.0f;

    for (int c = 0; c < nchunks; c++) {
        float4 v;
        const bool more = (c + 1 < nchunks);
        if (more) v = pk[((c + 1) << 8) + tid];

        const float4* __restrict__ buf = sb[c & 1];
        const int lo = c << 8;
        int a = jstart - lo; a = a < 0 ? 0 : (a > 256 ? 256 : a);
        int e = jend   - lo; e = e < 0 ? 0 : (e > 256 ? 256 : e);

        for (int jl = a; jl < e; jl += 8) {       // (e-a) % 16 == 0
            float4 p0 = buf[jl + 0]; float4 p1 = buf[jl + 1];
            float4 p2 = buf[jl + 2]; float4 p3 = buf[jl + 3];
            float4 p4 = buf[jl + 4]; float4 p5 = buf[jl + 5];
            float4 p6 = buf[jl + 6]; float4 p7 = buf[jl + 7];
            s0 += ex2f(fmaf(xi, p0.y, fmaf(yi, p0.z, p0.x)));
            s1 += ex2f(fmaf(xi, p1.y, fmaf(yi, p1.z, p1.x)));
            s2 += ex2f(fmaf(xi, p2.y, fmaf(yi, p2.z, p2.x)));
            s3 += ex2f(fmaf(xi, p3.y, fmaf(yi, p3.z, p3.x)));
            s0 += ex2f(fmaf(xi, p4.y, fmaf(yi, p4.z, p4.x)));
            s1 += ex2f(fmaf(xi, p5.y, fmaf(yi, p5.z, p5.x)));
            s2 += ex2f(fmaf(xi, p6.y, fmaf(yi, p6.z, p6.x)));
            s3 += ex2f(fmaf(xi, p7.y, fmaf(yi, p7.z, p7.x)));
        }

        // Triangular tail: j = 32*tile + jt, jt < lane
        if (dotail && ((tile >> 3) == c)) {
            const int base = (tile & 7) << 5;
#pragma unroll
            for (int jt = 0; jt < 31; jt++) {
                float4 q = buf[base + jt];
                float e2 = ex2f(fmaf(xi, q.y, fmaf(yi, q.z, q.x)));
                s1 += (jt < lane) ? e2 : 0.0f;
            }
        }

        __syncthreads();
        if (more) sb[(c + 1) & 1][tid] = v;
        __syncthreads();
    }

    sacc[wid][lane] = (s0 + s1) + (s2 + s3);
    __syncthreads();

    if (!(wid & 1)) {                      // wid 0,2,4,6 — one per tile
        float S = sacc[wid][lane] + sacc[wid + 1][lane];

        float res;
        if (i == 0) {
            const float mu0 = *mu0_p;
            const float ls0 = *ls0_p;
            const float iv  = __expf(-2.0f * ls0);
            const float dx = xi - mu0, dy = yi - mu0;
            res = -0.5f * iv * fmaf(dx, dx, dy * dy) - 2.0f * ls0 - LOG2PI_F;
        } else {
            const float B2 = -h2l * fmaf(xi, xi, yi * yi);
            const float K  = 2.0f * sls + LOG2PI_F;
            res = __logf(S) + LN2F * B2 - K - g_logP[n * TT + i];
        }
        out[n * TT + i] = res;
    }
}

// ---------------------------------------------------------------------------
extern "C" void kernel_launch(void* const* d_in, const int* in_sizes, int n_in,
                              void* d_out, int out_size) {
    const float* tim  = (const float*)d_in[0];  // (N, T, 1)
    const float* loc  = (const float*)d_in[1];  // (N, T, 2)
    const float* mu0  = (const float*)d_in[2];
    const float* ls0  = (const float*)d_in[3];
    const float* cd   = (const float*)d_in[4];
    const float* sls  = (const float*)d_in[5];
    float* out = (float*)d_out;

    const int N = in_sizes[0] / TT;             // 16

    prep_kernel<<<N, 256>>>(tim, loc, cd, sls);
    main_kernel<<<N * 16, 256>>>(loc, mu0, ls0, sls, out);
}